// round 1
// baseline (speedup 1.0000x reference)
#include <cuda_runtime.h>
#include <cstdint>
#include <climits>

// Problem constants (match reference)
#define NUM_MASKS 64
#define MH 1024
#define MW 1024
#define BLOCKS_PER_MASK 16
#define NTHREADS 256
#define AREA_THRESH 1024  // (1024/32)*(1024/32); keep = count > AREA_THRESH

// Per-mask accumulators (device-global scratch; reset each launch by init kernel)
__device__ int g_minx[NUM_MASKS];
__device__ int g_miny[NUM_MASKS];
__device__ int g_maxx[NUM_MASKS];
__device__ int g_maxy[NUM_MASKS];
__device__ int g_cnt [NUM_MASKS];

__global__ void fsam_init_kernel() {
    int i = threadIdx.x;
    if (i < NUM_MASKS) {
        g_minx[i] = INT_MAX;
        g_miny[i] = INT_MAX;
        g_maxx[i] = -1;
        g_maxy[i] = -1;
        g_cnt [i] = 0;
    }
}

__global__ __launch_bounds__(NTHREADS) void fsam_reduce_kernel(const float* __restrict__ masks) {
    const int mask = blockIdx.x / BLOCKS_PER_MASK;
    const int sub  = blockIdx.x % BLOCKS_PER_MASK;

    const uint4* __restrict__ base =
        reinterpret_cast<const uint4*>(masks + (size_t)mask * (MH * MW));
    const int NV = (MH * MW) / 4;                    // 262144 uint4 per mask
    const int stride = BLOCKS_PER_MASK * NTHREADS;   // 4096
    int i0 = sub * NTHREADS + threadIdx.x;

    int minx = INT_MAX, miny = INT_MAX;
    int maxx = -1, maxy = -1;
    int cnt = 0;
    const unsigned ONE = 0x3F800000u; // float 1.0f bit pattern

    #pragma unroll 4
    for (int i = i0; i < NV; i += stride) {
        uint4 v = base[i];
        unsigned m =  (unsigned)(v.x == ONE)
                   | ((unsigned)(v.y == ONE) << 1)
                   | ((unsigned)(v.z == ONE) << 2)
                   | ((unsigned)(v.w == ONE) << 3);
        cnt += __popc(m);
        if (m) {
            int row     = i >> 8;          // (4*i) / 1024
            int colbase = (i & 255) << 2;  // (4*i) % 1024
            miny = min(miny, row);
            maxy = max(maxy, row);
            minx = min(minx, colbase + (__ffs(m) - 1));
            maxx = max(maxx, colbase + (31 - __clz(m)));
        }
    }

    // Warp reduction
    #pragma unroll
    for (int off = 16; off > 0; off >>= 1) {
        minx = min(minx, __shfl_down_sync(0xFFFFFFFFu, minx, off));
        miny = min(miny, __shfl_down_sync(0xFFFFFFFFu, miny, off));
        maxx = max(maxx, __shfl_down_sync(0xFFFFFFFFu, maxx, off));
        maxy = max(maxy, __shfl_down_sync(0xFFFFFFFFu, maxy, off));
        cnt +=           __shfl_down_sync(0xFFFFFFFFu, cnt,  off);
    }

    __shared__ int s_minx[8], s_miny[8], s_maxx[8], s_maxy[8], s_cnt[8];
    const int wid  = threadIdx.x >> 5;
    const int lane = threadIdx.x & 31;
    if (lane == 0) {
        s_minx[wid] = minx; s_miny[wid] = miny;
        s_maxx[wid] = maxx; s_maxy[wid] = maxy;
        s_cnt [wid] = cnt;
    }
    __syncthreads();

    if (threadIdx.x == 0) {
        int bminx = s_minx[0], bminy = s_miny[0];
        int bmaxx = s_maxx[0], bmaxy = s_maxy[0];
        int bcnt  = s_cnt[0];
        #pragma unroll
        for (int j = 1; j < NTHREADS / 32; j++) {
            bminx = min(bminx, s_minx[j]);
            bminy = min(bminy, s_miny[j]);
            bmaxx = max(bmaxx, s_maxx[j]);
            bmaxy = max(bmaxy, s_maxy[j]);
            bcnt += s_cnt[j];
        }
        atomicMin(&g_minx[mask], bminx);
        atomicMin(&g_miny[mask], bminy);
        atomicMax(&g_maxx[mask], bmaxx);
        atomicMax(&g_maxy[mask], bmaxy);
        atomicAdd(&g_cnt [mask], bcnt);
    }
}

__global__ void fsam_finalize_kernel(float* __restrict__ out) {
    int m = threadIdx.x;
    if (m < NUM_MASKS) {
        bool keep = g_cnt[m] > AREA_THRESH;
        float4 b;
        if (keep) {
            b = make_float4((float)g_minx[m], (float)g_miny[m],
                            (float)g_maxx[m], (float)g_maxy[m]);
        } else {
            b = make_float4(0.f, 0.f, 0.f, 0.f);
        }
        reinterpret_cast<float4*>(out)[m] = b;
    }
}

extern "C" void kernel_launch(void* const* d_in, const int* in_sizes, int n_in,
                              void* d_out, int out_size) {
    const float* masks = (const float*)d_in[0];
    float* out = (float*)d_out;

    fsam_init_kernel<<<1, 64>>>();
    fsam_reduce_kernel<<<NUM_MASKS * BLOCKS_PER_MASK, NTHREADS>>>(masks);
    fsam_finalize_kernel<<<1, 64>>>(out);
}

// round 2
// speedup vs baseline: 1.0933x; 1.0933x over previous
#include <cuda_runtime.h>
#include <cstdint>
#include <climits>

#define NUM_MASKS 64
#define MH 1024
#define MW 1024
#define BLOCKS_PER_MASK 16
#define NTHREADS 256
#define NBLOCKS (NUM_MASKS * BLOCKS_PER_MASK)   // 1024
#define AREA_THRESH 1024   // (1024/32)*(1024/32); keep = count > AREA_THRESH

// Per-block partials. Every slot is written on every launch -> no init needed.
__device__ int g_pminx[NBLOCKS];
__device__ int g_pminy[NBLOCKS];
__device__ int g_pmaxx[NBLOCKS];
__device__ int g_pmaxy[NBLOCKS];
__device__ int g_pcnt [NBLOCKS];
// Arrival counter; the finalizing block resets it to 0 so graph replays see a
// clean state every launch (deterministic: exactly NBLOCKS arrivals/launch).
__device__ unsigned int g_arrive = 0;

__global__ __launch_bounds__(NTHREADS) void fsam_fused_kernel(
    const float* __restrict__ masks, float* __restrict__ out) {

    const int mask = blockIdx.x >> 4;         // / BLOCKS_PER_MASK
    const int sub  = blockIdx.x & 15;
    const int tid  = threadIdx.x;

    const uint4* __restrict__ base =
        reinterpret_cast<const uint4*>(masks + (size_t)mask * (MH * MW));

    // i = i0 + j*4096 over 262144 uint4 per mask.
    //   row(i)      = i >> 8   = sub + 16*j   (stride 4096 is a multiple of 256)
    //   col-base(i) = (i&255)*4 = tid*4       (constant per thread!)
    const int i0 = sub * NTHREADS + tid;
    const int colbase = tid << 2;

    uint4 cm = make_uint4(0u, 0u, 0u, 0u);     // column OR accumulator
    unsigned long long rowmask = 0ull;         // bit j: any active pixel at row sub+16j
    float fc0 = 0.f, fc1 = 0.f;                // exact counts (values are 0.0/1.0)

    #pragma unroll 8
    for (int j = 0; j < 64; j++) {
        uint4 v = __ldcs(&base[i0 + j * 4096]);
        cm.x |= v.x; cm.y |= v.y; cm.z |= v.z; cm.w |= v.w;
        unsigned any = (v.x | v.y) | (v.z | v.w);
        rowmask |= (unsigned long long)(any != 0u) << j;
        fc0 += __uint_as_float(v.x) + __uint_as_float(v.z);
        fc1 += __uint_as_float(v.y) + __uint_as_float(v.w);
    }

    int cnt = (int)(fc0 + fc1);
    unsigned mbits =  (unsigned)(cm.x != 0u)
                   | ((unsigned)(cm.y != 0u) << 1)
                   | ((unsigned)(cm.z != 0u) << 2)
                   | ((unsigned)(cm.w != 0u) << 3);

    int minx, maxx, miny, maxy;
    if (mbits) { minx = colbase + (__ffs(mbits) - 1); maxx = colbase + (31 - __clz(mbits)); }
    else       { minx = INT_MAX;                      maxx = -1; }
    if (rowmask) {
        miny = sub + ((__ffsll((long long)rowmask) - 1) << 4);
        maxy = sub + ((63 - __clzll((long long)rowmask)) << 4);
    } else { miny = INT_MAX; maxy = -1; }

    // ---- block reduction ----
    #pragma unroll
    for (int off = 16; off > 0; off >>= 1) {
        minx = min(minx, __shfl_down_sync(0xFFFFFFFFu, minx, off));
        miny = min(miny, __shfl_down_sync(0xFFFFFFFFu, miny, off));
        maxx = max(maxx, __shfl_down_sync(0xFFFFFFFFu, maxx, off));
        maxy = max(maxy, __shfl_down_sync(0xFFFFFFFFu, maxy, off));
        cnt +=           __shfl_down_sync(0xFFFFFFFFu, cnt,  off);
    }

    __shared__ int s_minx[8], s_miny[8], s_maxx[8], s_maxy[8], s_cnt[8];
    __shared__ unsigned s_last;
    const int wid  = tid >> 5;
    const int lane = tid & 31;
    if (lane == 0) {
        s_minx[wid] = minx; s_miny[wid] = miny;
        s_maxx[wid] = maxx; s_maxy[wid] = maxy;
        s_cnt [wid] = cnt;
    }
    __syncthreads();

    if (tid == 0) {
        int bminx = s_minx[0], bminy = s_miny[0];
        int bmaxx = s_maxx[0], bmaxy = s_maxy[0];
        int bcnt  = s_cnt[0];
        #pragma unroll
        for (int j = 1; j < NTHREADS / 32; j++) {
            bminx = min(bminx, s_minx[j]);
            bminy = min(bminy, s_miny[j]);
            bmaxx = max(bmaxx, s_maxx[j]);
            bmaxy = max(bmaxy, s_maxy[j]);
            bcnt += s_cnt[j];
        }
        g_pminx[blockIdx.x] = bminx;
        g_pminy[blockIdx.x] = bminy;
        g_pmaxx[blockIdx.x] = bmaxx;
        g_pmaxy[blockIdx.x] = bmaxy;
        g_pcnt [blockIdx.x] = bcnt;
        __threadfence();
        s_last = atomicAdd(&g_arrive, 1u);
    }
    __syncthreads();

    // ---- tail block: finalize ----
    if (s_last == NBLOCKS - 1) {
        __threadfence();  // acquire: see all partials
        // 256 threads: 4 threads per mask, each covers 4 of 16 partials.
        const int m = tid >> 2;
        const int p = tid & 3;
        int fminx = INT_MAX, fminy = INT_MAX, fmaxx = -1, fmaxy = -1, fcnt = 0;
        #pragma unroll
        for (int k = 0; k < 4; k++) {
            int idx = m * BLOCKS_PER_MASK + p + 4 * k;
            fminx = min(fminx, g_pminx[idx]);
            fminy = min(fminy, g_pminy[idx]);
            fmaxx = max(fmaxx, g_pmaxx[idx]);
            fmaxy = max(fmaxy, g_pmaxy[idx]);
            fcnt += g_pcnt[idx];
        }
        #pragma unroll
        for (int off = 2; off > 0; off >>= 1) {
            fminx = min(fminx, __shfl_down_sync(0xFFFFFFFFu, fminx, off));
            fminy = min(fminy, __shfl_down_sync(0xFFFFFFFFu, fminy, off));
            fmaxx = max(fmaxx, __shfl_down_sync(0xFFFFFFFFu, fmaxx, off));
            fmaxy = max(fmaxy, __shfl_down_sync(0xFFFFFFFFu, fmaxy, off));
            fcnt +=            __shfl_down_sync(0xFFFFFFFFu, fcnt,  off);
        }
        if (p == 0) {
            float4 b = (fcnt > AREA_THRESH)
                ? make_float4((float)fminx, (float)fminy, (float)fmaxx, (float)fmaxy)
                : make_float4(0.f, 0.f, 0.f, 0.f);
            reinterpret_cast<float4*>(out)[m] = b;
        }
        if (tid == 0) g_arrive = 0;  // reset for next graph replay
    }
}

extern "C" void kernel_launch(void* const* d_in, const int* in_sizes, int n_in,
                              void* d_out, int out_size) {
    const float* masks = (const float*)d_in[0];
    float* out = (float*)d_out;
    fsam_fused_kernel<<<NBLOCKS, NTHREADS>>>(masks, out);
}

// round 3
// speedup vs baseline: 1.1283x; 1.0321x over previous
#include <cuda_runtime.h>
#include <cstdint>
#include <climits>

#define NUM_MASKS 64
#define MH 1024
#define MW 1024
#define BLOCKS_PER_MASK 32
#define NTHREADS 256
#define NBLOCKS (NUM_MASKS * BLOCKS_PER_MASK)   // 2048
#define ITERS 32                                 // 262144 uint4 / (32*256)
#define AREA_THRESH 1024   // (1024/32)*(1024/32); keep = count > AREA_THRESH

// Per-block partials. Every slot is written on every launch -> no init needed.
__device__ int g_pminx[NBLOCKS];
__device__ int g_pminy[NBLOCKS];
__device__ int g_pmaxx[NBLOCKS];
__device__ int g_pmaxy[NBLOCKS];
__device__ int g_pcnt [NBLOCKS];
// Arrival counter; finalizing block resets it so graph replays start clean.
__device__ unsigned int g_arrive = 0;

__global__ __launch_bounds__(NTHREADS) void fsam_fused_kernel(
    const float* __restrict__ masks, float* __restrict__ out) {

    const int mask = blockIdx.x >> 5;          // / BLOCKS_PER_MASK
    const int sub  = blockIdx.x & 31;
    const int tid  = threadIdx.x;

    const uint4* __restrict__ base =
        reinterpret_cast<const uint4*>(masks + (size_t)mask * (MH * MW));

    // i = sub*256 + tid + j*8192 over 262144 uint4 per mask.
    //   row(i)      = i >> 8    = sub + 32*j
    //   col-base(i) = (i&255)*4 = tid*4   (constant per thread)
    const int i0 = sub * NTHREADS + tid;
    const int colbase = tid << 2;

    uint4 cm = make_uint4(0u, 0u, 0u, 0u);   // column OR accumulator
    unsigned rowmask = 0u;                   // bit j: any active pixel at row sub+32j
    float fc0 = 0.f, fc1 = 0.f, fc2 = 0.f, fc3 = 0.f;  // exact counts (0.0/1.0)

    #pragma unroll 8
    for (int j = 0; j < ITERS; j++) {
        uint4 v = base[i0 + j * 8192];
        cm.x |= v.x; cm.y |= v.y; cm.z |= v.z; cm.w |= v.w;
        unsigned any = (v.x | v.y) | (v.z | v.w);
        rowmask |= (unsigned)(any != 0u) << j;
        fc0 += __uint_as_float(v.x);
        fc1 += __uint_as_float(v.y);
        fc2 += __uint_as_float(v.z);
        fc3 += __uint_as_float(v.w);
    }

    int cnt = (int)((fc0 + fc1) + (fc2 + fc3));
    unsigned mbits =  (unsigned)(cm.x != 0u)
                   | ((unsigned)(cm.y != 0u) << 1)
                   | ((unsigned)(cm.z != 0u) << 2)
                   | ((unsigned)(cm.w != 0u) << 3);

    int minx, maxx, miny, maxy;
    if (mbits) { minx = colbase + (__ffs(mbits) - 1); maxx = colbase + (31 - __clz(mbits)); }
    else       { minx = INT_MAX;                      maxx = -1; }
    if (rowmask) {
        miny = sub + ((__ffs(rowmask) - 1) << 5);
        maxy = sub + ((31 - __clz(rowmask)) << 5);
    } else { miny = INT_MAX; maxy = -1; }

    // ---- block reduction ----
    #pragma unroll
    for (int off = 16; off > 0; off >>= 1) {
        minx = min(minx, __shfl_down_sync(0xFFFFFFFFu, minx, off));
        miny = min(miny, __shfl_down_sync(0xFFFFFFFFu, miny, off));
        maxx = max(maxx, __shfl_down_sync(0xFFFFFFFFu, maxx, off));
        maxy = max(maxy, __shfl_down_sync(0xFFFFFFFFu, maxy, off));
        cnt +=           __shfl_down_sync(0xFFFFFFFFu, cnt,  off);
    }

    __shared__ int s_minx[8], s_miny[8], s_maxx[8], s_maxy[8], s_cnt[8];
    __shared__ unsigned s_last;
    const int wid  = tid >> 5;
    const int lane = tid & 31;
    if (lane == 0) {
        s_minx[wid] = minx; s_miny[wid] = miny;
        s_maxx[wid] = maxx; s_maxy[wid] = maxy;
        s_cnt [wid] = cnt;
    }
    __syncthreads();

    if (tid == 0) {
        int bminx = s_minx[0], bminy = s_miny[0];
        int bmaxx = s_maxx[0], bmaxy = s_maxy[0];
        int bcnt  = s_cnt[0];
        #pragma unroll
        for (int j = 1; j < NTHREADS / 32; j++) {
            bminx = min(bminx, s_minx[j]);
            bminy = min(bminy, s_miny[j]);
            bmaxx = max(bmaxx, s_maxx[j]);
            bmaxy = max(bmaxy, s_maxy[j]);
            bcnt += s_cnt[j];
        }
        g_pminx[blockIdx.x] = bminx;
        g_pminy[blockIdx.x] = bminy;
        g_pmaxx[blockIdx.x] = bmaxx;
        g_pmaxy[blockIdx.x] = bmaxy;
        g_pcnt [blockIdx.x] = bcnt;
        __threadfence();
        s_last = atomicAdd(&g_arrive, 1u);
    }
    __syncthreads();

    // ---- tail block: finalize ----
    if (s_last == NBLOCKS - 1) {
        __threadfence();  // acquire: see all partials
        // 256 threads: 4 threads per mask, each covers 8 of 32 partials.
        const int m = tid >> 2;
        const int p = tid & 3;
        int fminx = INT_MAX, fminy = INT_MAX, fmaxx = -1, fmaxy = -1, fcnt = 0;
        #pragma unroll
        for (int k = 0; k < 8; k++) {
            int idx = m * BLOCKS_PER_MASK + p + 4 * k;
            fminx = min(fminx, g_pminx[idx]);
            fminy = min(fminy, g_pminy[idx]);
            fmaxx = max(fmaxx, g_pmaxx[idx]);
            fmaxy = max(fmaxy, g_pmaxy[idx]);
            fcnt += g_pcnt[idx];
        }
        #pragma unroll
        for (int off = 2; off > 0; off >>= 1) {
            fminx = min(fminx, __shfl_down_sync(0xFFFFFFFFu, fminx, off));
            fminy = min(fminy, __shfl_down_sync(0xFFFFFFFFu, fminy, off));
            fmaxx = max(fmaxx, __shfl_down_sync(0xFFFFFFFFu, fmaxx, off));
            fmaxy = max(fmaxy, __shfl_down_sync(0xFFFFFFFFu, fmaxy, off));
            fcnt +=            __shfl_down_sync(0xFFFFFFFFu, fcnt,  off);
        }
        if (p == 0) {
            float4 b = (fcnt > AREA_THRESH)
                ? make_float4((float)fminx, (float)fminy, (float)fmaxx, (float)fmaxy)
                : make_float4(0.f, 0.f, 0.f, 0.f);
            reinterpret_cast<float4*>(out)[m] = b;
        }
        if (tid == 0) g_arrive = 0;  // reset for next graph replay
    }
}

extern "C" void kernel_launch(void* const* d_in, const int* in_sizes, int n_in,
                              void* d_out, int out_size) {
    const float* masks = (const float*)d_in[0];
    float* out = (float*)d_out;
    fsam_fused_kernel<<<NBLOCKS, NTHREADS>>>(masks, out);
}